// round 1
// baseline (speedup 1.0000x reference)
#include <cuda_runtime.h>

// ---------------- problem constants ----------------
#define NB   32        // batch
#define CIN  256
#define COUT 512
#define HW   16        // 4x4 spatial
#define KTOT 65536     // CIN*CIN
#define S_SPLIT 128    // K-splits in main GEMM
#define KC 32          // K-chunk staged per iteration
#define CHUNKS_PER_SPLIT 16   // KTOT / (S_SPLIT*KC)

// ---------------- scratch (__device__ globals; no allocs allowed) ----------
__device__ float g_y[NB * CIN * HW];          // y[b][c'][hw]            512 KB
__device__ float g_xsum[NB * CIN];            // X[b][c]                  32 KB
__device__ float g_G[NB * KTOT];              // G[b][c*256+c']            8 MB
__device__ float g_part[S_SPLIT * NB * COUT]; // partials [s][b][o]        8 MB

// ============================================================
// K1: y = relu(W1 x + b1), and Xsum = sum_hw x
// grid (4, 32) = (cgroup, b), 256 threads
// ============================================================
__global__ void __launch_bounds__(256) k1_y(const float* __restrict__ x,
                                            const float* __restrict__ W1,
                                            const float* __restrict__ b1)
{
    __shared__ float xs[CIN * HW];   // 16 KB
    const int b  = blockIdx.y;
    const int cg = blockIdx.x;
    const int t  = threadIdx.x;

    // stage x[b] into smem (coalesced float4)
    {
        const float4* xv  = (const float4*)(x + (size_t)b * CIN * HW);
        float4*       xsv = (float4*)xs;
        for (int i = t; i < CIN * HW / 4; i += 256) xsv[i] = xv[i];
    }
    __syncthreads();

    const int cp  = cg * 64 + (t >> 2);   // output channel c'
    const int hw0 = (t & 3) * 4;          // this thread's 4 hw positions

    float bv = b1[cp];
    float a0 = bv, a1 = bv, a2 = bv, a3 = bv;

    const float4* w1v = (const float4*)(W1 + (size_t)cp * CIN);
    #pragma unroll 4
    for (int c4 = 0; c4 < CIN / 4; c4++) {
        float4 w = w1v[c4];
        const float* xp = xs + c4 * 4 * HW + hw0;
        a0 += w.x * xp[0];      a1 += w.x * xp[1];      a2 += w.x * xp[2];      a3 += w.x * xp[3];
        a0 += w.y * xp[16];     a1 += w.y * xp[17];     a2 += w.y * xp[18];     a3 += w.y * xp[19];
        a0 += w.z * xp[32];     a1 += w.z * xp[33];     a2 += w.z * xp[34];     a3 += w.z * xp[35];
        a0 += w.w * xp[48];     a1 += w.w * xp[49];     a2 += w.w * xp[50];     a3 += w.w * xp[51];
    }

    float4 r;
    r.x = fmaxf(a0, 0.f); r.y = fmaxf(a1, 0.f); r.z = fmaxf(a2, 0.f); r.w = fmaxf(a3, 0.f);
    *(float4*)(g_y + ((size_t)b * CIN + cp) * HW + hw0) = r;

    if (cg == 0) {   // Xsum[b][c], c = t
        float s = 0.f;
        #pragma unroll
        for (int h = 0; h < HW; h++) s += xs[t * HW + h];
        g_xsum[b * CIN + t] = s;
    }
}

// ============================================================
// K2: G[b][c*256+c'] = sum_hw x[b,c,hw]*y[b,c',hw]
// grid (8, 32) = (cgroup of 32 c-rows, b), 256 threads (thread = c')
// ============================================================
__global__ void __launch_bounds__(256) k2_G(const float* __restrict__ x)
{
    __shared__ float xs2[32 * HW];   // 2 KB: x rows c in [cg*32, cg*32+32)
    const int b  = blockIdx.y;
    const int cg = blockIdx.x;
    const int t  = threadIdx.x;

    {
        const float4* xv = (const float4*)(x + ((size_t)b * CIN + cg * 32) * HW);
        float4*       sv = (float4*)xs2;
        for (int i = t; i < 32 * HW / 4; i += 256) sv[i] = xv[i];
    }

    // y row for c' = t into registers (read-only, per-thread)
    float yr[HW];
    {
        const float4* yv = (const float4*)(g_y + ((size_t)b * CIN + t) * HW);
        #pragma unroll
        for (int i = 0; i < 4; i++) {
            float4 v = yv[i];
            yr[i * 4 + 0] = v.x; yr[i * 4 + 1] = v.y; yr[i * 4 + 2] = v.z; yr[i * 4 + 3] = v.w;
        }
    }
    __syncthreads();

    float* Gb = g_G + (size_t)b * KTOT + cg * 32 * 256 + t;
    #pragma unroll 4
    for (int j = 0; j < 32; j++) {       // c within tile; xs2 access is warp-broadcast
        const float* xj = xs2 + j * HW;
        float v = 0.f;
        #pragma unroll
        for (int h = 0; h < HW; h++) v += xj[h] * yr[h];
        Gb[(size_t)j * 256] = v;         // coalesced across threads
    }
}

// ============================================================
// K3: main GEMM partials: part[s][b][o] = sum_{k in slice} G[b][k]*W2v[o][k]
//   W2v[o][k] = W2[o*65536 + k]  (W2 given as [131072,256] row-major)
// grid (4, 128) = (o-tile of 128, k-split), 128 threads
// thread tile: 8 b  x  4 o   (warp = one b-group of 8; lane -> 4 consecutive o)
// ============================================================
__global__ void __launch_bounds__(128) k3_gemm(const float* __restrict__ W2)
{
    __shared__ float sG[32][36];   // [b][kk] padded; compute reads are warp-broadcast

    const int og   = blockIdx.x;
    const int s    = blockIdx.y;
    const int tid  = threadIdx.x;
    const int lane = tid & 31;
    const int bg   = tid >> 5;          // warp id = b-group
    const int o0   = og * 128 + lane * 4;

    float acc[8][4];
    #pragma unroll
    for (int i = 0; i < 8; i++)
        #pragma unroll
        for (int j = 0; j < 4; j++) acc[i][j] = 0.f;

    const float* w2r0 = W2 + (size_t)(o0 + 0) * KTOT;
    const float* w2r1 = W2 + (size_t)(o0 + 1) * KTOT;
    const float* w2r2 = W2 + (size_t)(o0 + 2) * KTOT;
    const float* w2r3 = W2 + (size_t)(o0 + 3) * KTOT;

    const int kbase = s * (CHUNKS_PER_SPLIT * KC);

    for (int ch = 0; ch < CHUNKS_PER_SPLIT; ch++) {
        const int k0 = kbase + ch * KC;

        // stage G tile [32 b][32 kk] -> sG (coalesced loads, conflict-free stores)
        __syncthreads();
        #pragma unroll
        for (int p = 0; p < 2; p++) {
            int q   = tid + p * 128;      // 0..255 float4 slots
            int bb  = q >> 3;             // 0..31
            int kk4 = q & 7;              // 0..7
            float4 v = *((const float4*)(g_G + (size_t)bb * KTOT + k0) + kk4);
            *((float4*)(&sG[bb][0]) + kk4) = v;
        }
        __syncthreads();

        #pragma unroll
        for (int kq = 0; kq < KC / 4; kq++) {
            float4 w0 = *(const float4*)(w2r0 + k0 + kq * 4);
            float4 w1 = *(const float4*)(w2r1 + k0 + kq * 4);
            float4 w2v = *(const float4*)(w2r2 + k0 + kq * 4);
            float4 w3 = *(const float4*)(w2r3 + k0 + kq * 4);
            #pragma unroll
            for (int i = 0; i < 8; i++) {
                float4 g = *((const float4*)(&sG[bg * 8 + i][0]) + kq);  // broadcast
                acc[i][0] += g.x * w0.x + g.y * w0.y + g.z * w0.z + g.w * w0.w;
                acc[i][1] += g.x * w1.x + g.y * w1.y + g.z * w1.z + g.w * w1.w;
                acc[i][2] += g.x * w2v.x + g.y * w2v.y + g.z * w2v.z + g.w * w2v.w;
                acc[i][3] += g.x * w3.x + g.y * w3.y + g.z * w3.z + g.w * w3.w;
            }
        }
    }

    #pragma unroll
    for (int i = 0; i < 8; i++) {
        int b = bg * 8 + i;
        float4 v = make_float4(acc[i][0], acc[i][1], acc[i][2], acc[i][3]);
        *(float4*)(g_part + ((size_t)s * NB + b) * COUT + o0) = v;   // coalesced
    }
}

// ============================================================
// K4: out[b][o] = sum_s part[s][b][o] + sum_c b2[o*256+c]*Xsum[b][c]
// grid 128 blocks x 128 threads  (16384 outputs)
// ============================================================
__global__ void __launch_bounds__(128) k4_reduce(const float* __restrict__ b2,
                                                 float* __restrict__ out)
{
    const int m = blockIdx.x * 128 + threadIdx.x;   // 0..16383
    const int b = m >> 9;
    const int o = m & 511;

    float s = 0.f;
    #pragma unroll 8
    for (int sp = 0; sp < S_SPLIT; sp++)
        s += g_part[(size_t)sp * (NB * COUT) + m];   // coalesced

    const float* b2r = b2 + (size_t)o * CIN;
    const float* xr  = g_xsum + b * CIN;             // warp-uniform (broadcast)
    float bias = 0.f;
    #pragma unroll 8
    for (int c = 0; c < CIN; c++) bias += b2r[c] * xr[c];

    out[m] = s + bias;
}

// ============================================================
extern "C" void kernel_launch(void* const* d_in, const int* in_sizes, int n_in,
                              void* d_out, int out_size)
{
    const float* x  = (const float*)d_in[0];
    const float* W1 = (const float*)d_in[1];
    const float* b1 = (const float*)d_in[2];
    const float* W2 = (const float*)d_in[3];
    const float* b2 = (const float*)d_in[4];
    // d_in[5] (Wa), d_in[6] (ba): attention branch is dead code in the reference.
    float* out = (float*)d_out;

    k1_y<<<dim3(4, NB), 256>>>(x, W1, b1);
    k2_G<<<dim3(8, NB), 256>>>(x);
    k3_gemm<<<dim3(4, S_SPLIT), 128>>>(W2);
    k4_reduce<<<dim3((NB * COUT) / 128), 128>>>(b2, out);
}